// round 14
// baseline (speedup 1.0000x reference)
#include <cuda_runtime.h>
#include <cuda_bf16.h>
#include <cstdint>

// ---------------------------------------------------------------------------
// MambaBlock: B=4, L=1024, D_MODEL=768, D_INNER=1536, D_STATE=16, DT_RANK=48
// Big GEMMs: mma.sync.m16n8k16.bf16.  Small GEMMs: tf32.
// Scan: 16 lanes per (b,d) (1 state/lane), PF=8 prefetch ring.
// xproj: split-K x6 + reduce.
// ---------------------------------------------------------------------------

#define Bsz 4
#define Lsz 1024
#define DM  768
#define DI  1536
#define DS  16
#define DTR 48
#define MROWS (Bsz * Lsz)   // 4096
#define SPLITK 6
#define XPK (DI / SPLITK)   // 256

__device__ __align__(16) __nv_bfloat16 g_hn_bf [MROWS * DM];
__device__ __align__(16) __nv_bfloat16 g_Win_bf[2 * DI * DM];
__device__ __align__(16) __nv_bfloat16 g_Wout_bf[DM * DI];
__device__ __align__(16) __nv_bfloat16 g_y_bf  [MROWS * DI];
__device__ __align__(16) float g_xz  [MROWS * 2 * DI];
__device__ __align__(16) float g_xssm[MROWS * DI];
__device__ __align__(16) float g_xdbl[MROWS * 80];
__device__ __align__(16) float g_xdbl_part[SPLITK * MROWS * 80];
__device__ __align__(16) float g_dt  [MROWS * DI];
__device__ __align__(16) float g_stats[MROWS * 2];

// ---------------------------------------------------------------------------
// fp32 -> bf16 conversion (weights)
// ---------------------------------------------------------------------------
__global__ void cvt_bf16_kernel(const float* __restrict__ src,
                                __nv_bfloat16* __restrict__ dst, int n)
{
    int i = blockIdx.x * blockDim.x + threadIdx.x;
    if (i < n) dst[i] = __float2bfloat16_rn(src[i]);
}

// ---------------------------------------------------------------------------
// 1) LayerNorm statistics
// ---------------------------------------------------------------------------
__global__ void ln_stats_kernel(const float* __restrict__ x)
{
    __shared__ float s_sum[256];
    __shared__ float s_sq[256];
    int tid  = threadIdx.x;
    int lid  = tid & 63;
    int part = tid >> 6;
    int b    = blockIdx.y;
    int l    = blockIdx.x * 64 + lid;
    const float* xb = x + (size_t)b * DM * Lsz + l;

    float sum = 0.f, sq = 0.f;
    int c0 = part * (DM / 4);
    #pragma unroll 8
    for (int c = c0; c < c0 + DM / 4; c++) {
        float v = xb[(size_t)c * Lsz];
        sum += v;
        sq  += v * v;
    }
    s_sum[tid] = sum;
    s_sq[tid]  = sq;
    __syncthreads();
    if (part == 0) {
        float ts = s_sum[tid] + s_sum[tid + 64] + s_sum[tid + 128] + s_sum[tid + 192];
        float tq = s_sq[tid]  + s_sq[tid + 64]  + s_sq[tid + 128]  + s_sq[tid + 192];
        float mu = ts / DM;
        float var = tq / DM - mu * mu;
        float rstd = rsqrtf(var + 1e-5f);
        int bl = b * Lsz + l;
        g_stats[bl * 2 + 0] = mu;
        g_stats[bl * 2 + 1] = rstd;
    }
}

// ---------------------------------------------------------------------------
// 2) Transpose (B,C,L)->(B*L,C) with LN applied; bf16 output.
// ---------------------------------------------------------------------------
__global__ void ln_apply_kernel(const float* __restrict__ x,
                                const float* __restrict__ gamma,
                                const float* __restrict__ beta)
{
    __shared__ float tile[32][33];
    int b  = blockIdx.z;
    int c0 = blockIdx.y * 32;
    int l0 = blockIdx.x * 32;
    const float* xb = x + (size_t)b * DM * Lsz;

    #pragma unroll
    for (int i0 = 0; i0 < 4; i0++) {
        int c = c0 + threadIdx.y + i0 * 8;
        tile[threadIdx.y + i0 * 8][threadIdx.x] = xb[(size_t)c * Lsz + l0 + threadIdx.x];
    }
    __syncthreads();
    #pragma unroll
    for (int i0 = 0; i0 < 4; i0++) {
        int l  = l0 + threadIdx.y + i0 * 8;
        int c  = c0 + threadIdx.x;
        int bl = b * Lsz + l;
        float mu   = g_stats[bl * 2 + 0];
        float rstd = g_stats[bl * 2 + 1];
        float v = tile[threadIdx.x][threadIdx.y + i0 * 8];
        g_hn_bf[(size_t)bl * DM + c] =
            __float2bfloat16_rn((v - mu) * rstd * gamma[c] + beta[c]);
    }
}

// ---------------------------------------------------------------------------
// mma + cp.async helpers
// ---------------------------------------------------------------------------
__device__ __forceinline__ void mma_tf32(float* c, const uint32_t* a, const uint32_t* b)
{
    asm volatile(
        "mma.sync.aligned.m16n8k8.row.col.f32.tf32.tf32.f32 "
        "{%0,%1,%2,%3}, {%4,%5,%6,%7}, {%8,%9}, {%0,%1,%2,%3};"
        : "+f"(c[0]), "+f"(c[1]), "+f"(c[2]), "+f"(c[3])
        : "r"(a[0]), "r"(a[1]), "r"(a[2]), "r"(a[3]), "r"(b[0]), "r"(b[1]));
}

__device__ __forceinline__ void mma_bf16(float* c, const uint32_t* a, const uint32_t* b)
{
    asm volatile(
        "mma.sync.aligned.m16n8k16.row.col.f32.bf16.bf16.f32 "
        "{%0,%1,%2,%3}, {%4,%5,%6,%7}, {%8,%9}, {%0,%1,%2,%3};"
        : "+f"(c[0]), "+f"(c[1]), "+f"(c[2]), "+f"(c[3])
        : "r"(a[0]), "r"(a[1]), "r"(a[2]), "r"(a[3]), "r"(b[0]), "r"(b[1]));
}

__device__ __forceinline__ void cp16(uint32_t dst_smem, const void* src)
{
    asm volatile("cp.async.cg.shared.global [%0], [%1], 16;"
                 :: "r"(dst_smem), "l"(src));
}
__device__ __forceinline__ void cp_commit()
{
    asm volatile("cp.async.commit_group;");
}
template<int N>
__device__ __forceinline__ void cp_wait()
{
    asm volatile("cp.async.wait_group %0;" :: "n"(N));
}

// ---------------------------------------------------------------------------
// bf16 tensor GEMM:  C[M,N] = A[M,K] * B[N,K]^T  (A,B bf16 row-major, C fp32)
// BM=BN=128, BK=32, 128 threads (2x2 warps, 64x64 tiles), 3-stage cp.async.
// EPI 0: plain coalesced store.  EPI 2: transpose store + residual.
// ---------------------------------------------------------------------------
template<int EPI>
__global__ void __launch_bounds__(128, 3)
gemm_bf16(const __nv_bfloat16* __restrict__ A, int lda,
          const __nv_bfloat16* __restrict__ B, int ldb,
          float* __restrict__ C, int ldc,
          int K, const float* __restrict__ xres)
{
    constexpr int NTH = 128;
    constexpr int BM = 128;
    constexpr int MT = 4, NT = 8;       // 64x64 warp tile
    constexpr int LDT = 20;             // words per row (16 data + 4 pad)
    constexpr int ST  = 3;
    constexpr int STG = BM * LDT;       // words per stage per matrix

    extern __shared__ uint32_t smem[];
    uint32_t* Asm = smem;
    uint32_t* Bsm = smem + ST * STG;

    const int tid   = threadIdx.x;
    const int warp  = tid >> 5;
    const int lane  = tid & 31;
    const int g     = lane >> 2;
    const int t     = lane & 3;

    const int wm0 = (warp >> 1) * 64;
    const int wn0 = (warp & 1) * 64;

    const int m0 = blockIdx.y * BM;
    const int n0 = blockIdx.x * BM;

    const int niter = K / 32;

    float acc[MT][NT][4];
    #pragma unroll
    for (int i = 0; i < MT; i++)
        #pragma unroll
        for (int j = 0; j < NT; j++)
            #pragma unroll
            for (int q = 0; q < 4; q++) acc[i][j][q] = 0.f;

    uint32_t sA = (uint32_t)__cvta_generic_to_shared(Asm);
    uint32_t sB = (uint32_t)__cvta_generic_to_shared(Bsm);

    auto issue = [&](int s, int it) {
        int k0 = it * 32;
        uint32_t baseA = sA + (uint32_t)s * (STG * 4);
        uint32_t baseB = sB + (uint32_t)s * (STG * 4);
        #pragma unroll
        for (int i = 0; i < 512 / NTH; i++) {
            int id = tid + NTH * i;
            int r  = id >> 2;
            int c  = id & 3;
            cp16(baseA + (uint32_t)(r * LDT + c * 4) * 4,
                 &A[(size_t)(m0 + r) * lda + k0 + c * 8]);
            cp16(baseB + (uint32_t)(r * LDT + c * 4) * 4,
                 &B[(size_t)(n0 + r) * ldb + k0 + c * 8]);
        }
    };

    issue(0, 0); cp_commit();
    issue(1, 1); cp_commit();

    for (int it = 0; it < niter; it++) {
        const int s = it % ST;
        cp_wait<1>();
        __syncthreads();

        if (it + 2 < niter) issue((it + 2) % ST, it + 2);
        cp_commit();

        const uint32_t* as = Asm + s * STG;
        const uint32_t* bs = Bsm + s * STG;
        #pragma unroll
        for (int ks = 0; ks < 2; ks++) {
            const int kk = ks * 8;
            uint32_t afr[MT][4];
            uint32_t bfr[NT][2];
            #pragma unroll
            for (int i = 0; i < MT; i++) {
                int base = wm0 + 16 * i;
                afr[i][0] = as[(base + g)     * LDT + kk + t];
                afr[i][1] = as[(base + g + 8) * LDT + kk + t];
                afr[i][2] = as[(base + g)     * LDT + kk + 4 + t];
                afr[i][3] = as[(base + g + 8) * LDT + kk + 4 + t];
            }
            #pragma unroll
            for (int j = 0; j < NT; j++) {
                int bb = wn0 + 8 * j;
                bfr[j][0] = bs[(bb + g) * LDT + kk + t];
                bfr[j][1] = bs[(bb + g) * LDT + kk + 4 + t];
            }
            #pragma unroll
            for (int i = 0; i < MT; i++)
                #pragma unroll
                for (int j = 0; j < NT; j++)
                    mma_bf16(acc[i][j], afr[i], bfr[j]);
        }
    }

    #pragma unroll
    for (int i = 0; i < MT; i++) {
        int r0 = m0 + wm0 + 16 * i + g;
        int r1 = r0 + 8;
        #pragma unroll
        for (int j = 0; j < NT; j++) {
            int col = n0 + wn0 + 8 * j + 2 * t;
            float c0 = acc[i][j][0], c1 = acc[i][j][1];
            float c2 = acc[i][j][2], c3 = acc[i][j][3];
            if (EPI == 2) {
                int b0i = r0 >> 10, l0i = r0 & 1023;
                int b1i = r1 >> 10, l1i = r1 & 1023;
                size_t o00 = ((size_t)(b0i * DM + col))     * Lsz + l0i;
                size_t o01 = ((size_t)(b0i * DM + col + 1)) * Lsz + l0i;
                size_t o10 = ((size_t)(b1i * DM + col))     * Lsz + l1i;
                size_t o11 = ((size_t)(b1i * DM + col + 1)) * Lsz + l1i;
                C[o00] = c0 + xres[o00];
                C[o01] = c1 + xres[o01];
                C[o10] = c2 + xres[o10];
                C[o11] = c3 + xres[o11];
            } else {
                *reinterpret_cast<float2*>(&C[(size_t)r0 * ldc + col]) = make_float2(c0, c1);
                *reinterpret_cast<float2*>(&C[(size_t)r1 * ldc + col]) = make_float2(c2, c3);
            }
        }
    }
}

// ---------------------------------------------------------------------------
// tf32 tensor GEMM (small GEMMs: xproj split-K, dt).
// ---------------------------------------------------------------------------
template<int BN, int WARPS_M, int WARPS_N, int EPI>
__global__ void __launch_bounds__(32 * WARPS_M * WARPS_N, 3)
gemm_tf32(const float* __restrict__ A, int lda,
          const float* __restrict__ B, int ldb,
          float* __restrict__ C, int ldc,
          int K,
          const float* __restrict__ bias,
          int split_stride)
{
    constexpr int NTH = 32 * WARPS_M * WARPS_N;
    constexpr int BM = 128;
    constexpr int WM = BM / WARPS_M;
    constexpr int WN = BN / WARPS_N;
    constexpr int MT = WM / 16;
    constexpr int NT = WN / 8;
    constexpr int LDT = 20;
    constexpr int NA4 = BM * 4;
    constexpr int NB4 = BN * 4;
    constexpr int ST  = 3;
    constexpr int ASTG = BM * LDT;
    constexpr int BSTG = BN * LDT;

    extern __shared__ uint32_t smem[];
    uint32_t* Asm = smem;
    uint32_t* Bsm = smem + ST * ASTG;

    const int tid   = threadIdx.x;
    const int warp  = tid >> 5;
    const int lane  = tid & 31;
    const int g     = lane >> 2;
    const int t     = lane & 3;

    const int warp_m = warp / WARPS_N;
    const int warp_n = warp % WARPS_N;
    const int wm0 = warp_m * WM;
    const int wn0 = warp_n * WN;

    const int m0 = blockIdx.y * BM;
    const int n0 = blockIdx.x * BN;

    const float* Ae = A + (size_t)blockIdx.z * K;
    const float* Be = B + (size_t)blockIdx.z * K;
    float* Ce = C + (size_t)blockIdx.z * split_stride;

    const int niter = K / 16;

    float acc[MT][NT][4];
    #pragma unroll
    for (int i = 0; i < MT; i++)
        #pragma unroll
        for (int j = 0; j < NT; j++)
            #pragma unroll
            for (int q = 0; q < 4; q++) acc[i][j][q] = 0.f;

    uint32_t sA = (uint32_t)__cvta_generic_to_shared(Asm);
    uint32_t sB = (uint32_t)__cvta_generic_to_shared(Bsm);

    auto issue = [&](int s, int it) {
        int k0 = it * 16;
        uint32_t baseA = sA + (uint32_t)s * (ASTG * 4);
        #pragma unroll
        for (int i = 0; i < NA4 / NTH; i++) {
            int id = tid + NTH * i;
            int r  = id >> 2;
            int kq = (id & 3) * 4;
            cp16(baseA + (uint32_t)(r * LDT + kq) * 4,
                 &Ae[(size_t)(m0 + r) * lda + k0 + kq]);
        }
        uint32_t baseB = sB + (uint32_t)s * (BSTG * 4);
        #pragma unroll
        for (int i = 0; i < (NB4 + NTH - 1) / NTH; i++) {
            int id = tid + NTH * i;
            if (id < NB4) {
                int r  = id >> 2;
                int kq = (id & 3) * 4;
                cp16(baseB + (uint32_t)(r * LDT + kq) * 4,
                     &Be[(size_t)(n0 + r) * ldb + k0 + kq]);
            }
        }
    };

    issue(0, 0); cp_commit();
    issue(1, 1); cp_commit();

    for (int it = 0; it < niter; it++) {
        const int s = it % ST;
        cp_wait<1>();
        __syncthreads();

        if (it + 2 < niter) issue((it + 2) % ST, it + 2);
        cp_commit();

        const uint32_t* as = Asm + s * ASTG;
        const uint32_t* bs = Bsm + s * BSTG;
        #pragma unroll
        for (int ks = 0; ks < 2; ks++) {
            const int kk = ks * 8;
            uint32_t afr[MT][4];
            uint32_t bfr[NT][2];
            #pragma unroll
            for (int i = 0; i < MT; i++) {
                int base = wm0 + 16 * i;
                afr[i][0] = as[(base + g)     * LDT + kk + t];
                afr[i][1] = as[(base + g + 8) * LDT + kk + t];
                afr[i][2] = as[(base + g)     * LDT + kk + t + 4];
                afr[i][3] = as[(base + g + 8) * LDT + kk + t + 4];
            }
            #pragma unroll
            for (int j = 0; j < NT; j++) {
                int bb = wn0 + 8 * j;
                bfr[j][0] = bs[(bb + g) * LDT + kk + t];
                bfr[j][1] = bs[(bb + g) * LDT + kk + t + 4];
            }
            #pragma unroll
            for (int i = 0; i < MT; i++)
                #pragma unroll
                for (int j = 0; j < NT; j++)
                    mma_tf32(acc[i][j], afr[i], bfr[j]);
        }
    }

    #pragma unroll
    for (int i = 0; i < MT; i++) {
        int r0 = m0 + wm0 + 16 * i + g;
        int r1 = r0 + 8;
        #pragma unroll
        for (int j = 0; j < NT; j++) {
            int col = n0 + wn0 + 8 * j + 2 * t;
            float c0 = acc[i][j][0], c1 = acc[i][j][1];
            float c2 = acc[i][j][2], c3 = acc[i][j][3];
            if (EPI == 1) {
                float b0 = bias[col], b1 = bias[col + 1];
                c0 += b0; c1 += b1; c2 += b0; c3 += b1;
                c0 = (c0 > 20.f) ? c0 : log1pf(expf(c0));
                c1 = (c1 > 20.f) ? c1 : log1pf(expf(c1));
                c2 = (c2 > 20.f) ? c2 : log1pf(expf(c2));
                c3 = (c3 > 20.f) ? c3 : log1pf(expf(c3));
            }
            *reinterpret_cast<float2*>(&Ce[(size_t)r0 * ldc + col]) = make_float2(c0, c1);
            *reinterpret_cast<float2*>(&Ce[(size_t)r1 * ldc + col]) = make_float2(c2, c3);
        }
    }
}

#define GSMEM(BN) (3 * (128 + (BN)) * 20 * 4)
#define GSMEM_BF  (3 * 2 * 128 * 20 * 4)

// reduce the SPLITK partial xproj results -> g_xdbl (deterministic order)
__global__ void xdbl_reduce_kernel()
{
    int idx = blockIdx.x * blockDim.x + threadIdx.x;
    if (idx >= MROWS * 80) return;
    float s = 0.f;
    #pragma unroll
    for (int p = 0; p < SPLITK; p++)
        s += g_xdbl_part[(size_t)p * (MROWS * 80) + idx];
    g_xdbl[idx] = s;
}

// ---------------------------------------------------------------------------
// 4) depthwise causal conv(4) + bias + silu
// ---------------------------------------------------------------------------
__global__ void conv_silu_kernel(const float* __restrict__ conv_w,
                                 const float* __restrict__ conv_b)
{
    int idx = blockIdx.x * blockDim.x + threadIdx.x;
    if (idx >= MROWS * DI) return;
    int d  = idx % DI;
    int bl = idx / DI;
    int l  = bl & (Lsz - 1);

    float acc = conv_b[d];
    #pragma unroll
    for (int j = 0; j < 4; j++) {
        int ll = l - 3 + j;
        if (ll >= 0)
            acc += conv_w[d * 4 + j] * g_xz[(size_t)(bl - 3 + j) * (2 * DI) + d];
    }
    g_xssm[idx] = acc / (1.f + expf(-acc));
}

// ---------------------------------------------------------------------------
// 7) selective scan: 16 lanes per (b,d), 1 state per lane, PF=8 ring.
// 256 threads/block = 16 pairs; grid = 6144/16 = 384 blocks (~21 warps/SM).
// ---------------------------------------------------------------------------
#define PF 8

__global__ void __launch_bounds__(256)
scan_kernel(const float* __restrict__ A_log,
            const float* __restrict__ Dw)
{
    int pair = blockIdx.x * 16 + (threadIdx.x >> 4);
    if (pair >= Bsz * DI) return;
    int lane = threadIdx.x & 15;      // state index
    int b = pair / DI;
    int d = pair % DI;

    float Av = -expf(A_log[d * DS + lane]);
    float h  = 0.f;
    float Dd = Dw[d];

    const float* dtp = g_dt   + (size_t)b * Lsz * DI + d;
    const float* xp  = g_xssm + (size_t)b * Lsz * DI + d;
    const float* dbl = g_xdbl + (size_t)b * Lsz * 80;
    const float* zp  = g_xz   + (size_t)b * Lsz * (2 * DI) + DI + d;
    __nv_bfloat16* yp = g_y_bf + (size_t)b * Lsz * DI + d;

    float pdt[PF], px[PF], pz[PF], pB[PF], pC[PF];

    #pragma unroll
    for (int j = 0; j < PF; j++) {
        pdt[j] = dtp[(size_t)j * DI];
        px[j]  = xp [(size_t)j * DI];
        pB[j]  = dbl[j * 80 + DTR + lane];
        pC[j]  = dbl[j * 80 + DTR + DS + lane];
        pz[j]  = zp[(size_t)j * (2 * DI)];
    }

    for (int l0 = 0; l0 < Lsz; l0 += PF) {
        #pragma unroll
        for (int j = 0; j < PF; j++) {
            const int l = l0 + j;
            float dt_t = pdt[j];
            float x_t  = px[j];
            float Bv   = pB[j];
            float Cv   = pC[j];
            float zv   = pz[j];
            const int lf = l + PF;
            if (lf < Lsz) {
                pdt[j] = dtp[(size_t)lf * DI];
                px[j]  = xp [(size_t)lf * DI];
                pB[j]  = dbl[lf * 80 + DTR + lane];
                pC[j]  = dbl[lf * 80 + DTR + DS + lane];
                pz[j]  = zp[(size_t)lf * (2 * DI)];
            }
            h = expf(dt_t * Av) * h + (dt_t * x_t) * Bv;
            float part = h * Cv;
            part += __shfl_xor_sync(0xFFFFFFFFu, part, 8);
            part += __shfl_xor_sync(0xFFFFFFFFu, part, 4);
            part += __shfl_xor_sync(0xFFFFFFFFu, part, 2);
            part += __shfl_xor_sync(0xFFFFFFFFu, part, 1);
            if (lane == 0) {
                float sz = zv / (1.f + expf(-zv));
                yp[(size_t)l * DI] = __float2bfloat16_rn((part + Dd * x_t) * sz);
            }
        }
    }
}

// ---------------------------------------------------------------------------
extern "C" void kernel_launch(void* const* d_in, const int* in_sizes, int n_in,
                              void* d_out, int out_size)
{
    const float* x      = (const float*)d_in[0];
    const float* gamma  = (const float*)d_in[1];
    const float* beta   = (const float*)d_in[2];
    const float* W_in   = (const float*)d_in[3];
    const float* conv_w = (const float*)d_in[4];
    const float* conv_b = (const float*)d_in[5];
    const float* W_xproj= (const float*)d_in[6];
    const float* W_dt   = (const float*)d_in[7];
    const float* b_dt   = (const float*)d_in[8];
    const float* A_log  = (const float*)d_in[9];
    const float* Dw     = (const float*)d_in[10];
    const float* W_out  = (const float*)d_in[11];
    float* out = (float*)d_out;

    static float *xz = nullptr, *xssm = nullptr, *xdbl = nullptr,
                 *xdbl_part = nullptr, *dtb = nullptr;
    static __nv_bfloat16 *hn_bf = nullptr, *Win_bf = nullptr,
                         *Wout_bf = nullptr, *y_bf = nullptr;
    if (!xz) {
        cudaGetSymbolAddress((void**)&xz,        g_xz);
        cudaGetSymbolAddress((void**)&xssm,      g_xssm);
        cudaGetSymbolAddress((void**)&xdbl,      g_xdbl);
        cudaGetSymbolAddress((void**)&xdbl_part, g_xdbl_part);
        cudaGetSymbolAddress((void**)&dtb,       g_dt);
        cudaGetSymbolAddress((void**)&hn_bf,     g_hn_bf);
        cudaGetSymbolAddress((void**)&Win_bf,    g_Win_bf);
        cudaGetSymbolAddress((void**)&Wout_bf,   g_Wout_bf);
        cudaGetSymbolAddress((void**)&y_bf,      g_y_bf);
        cudaFuncSetAttribute(gemm_bf16<0>,
                             cudaFuncAttributeMaxDynamicSharedMemorySize, GSMEM_BF);
        cudaFuncSetAttribute(gemm_bf16<2>,
                             cudaFuncAttributeMaxDynamicSharedMemorySize, GSMEM_BF);
        cudaFuncSetAttribute(gemm_tf32<128, 2, 2, 1>,
                             cudaFuncAttributeMaxDynamicSharedMemorySize, GSMEM(128));
        cudaFuncSetAttribute(gemm_tf32<80, 4, 1, 0>,
                             cudaFuncAttributeMaxDynamicSharedMemorySize, GSMEM(80));
    }

    // 0) convert W_in to bf16 (keeps GEMM1 at profiled launch index 3)
    cvt_bf16_kernel<<<(2 * DI * DM + 255) / 256, 256>>>(W_in, Win_bf, 2 * DI * DM);
    // 1) LN stats
    ln_stats_kernel<<<dim3(Lsz / 64, Bsz), 256>>>(x);
    // 2) transpose + LN apply (bf16 out)
    ln_apply_kernel<<<dim3(Lsz / 32, DM / 32, Bsz), dim3(32, 8)>>>(x, gamma, beta);
    // 3) GEMM1 (bf16): xz = hn @ W_in^T   (4096 x 3072 x 768)
    gemm_bf16<0><<<dim3(3072 / 128, MROWS / 128), 128, GSMEM_BF>>>(
        hn_bf, DM, Win_bf, DM, xz, 2 * DI, DM, nullptr);
    // 4) conv + silu
    conv_silu_kernel<<<(MROWS * DI + 255) / 256, 256>>>(conv_w, conv_b);
    // 5) xproj split-K x6 + reduce
    gemm_tf32<80, 4, 1, 0><<<dim3(1, MROWS / 128, SPLITK), 128, GSMEM(80)>>>(
        xssm, DI, W_xproj, DI, xdbl_part, 80, XPK, nullptr, MROWS * 80);
    xdbl_reduce_kernel<<<(MROWS * 80 + 255) / 256, 256>>>();
    // 6) dt = softplus(xdbl[:, :48] @ W_dt^T + b_dt)
    gemm_tf32<128, 2, 2, 1><<<dim3(DI / 128, MROWS / 128), 128, GSMEM(128)>>>(
        xdbl, 80, W_dt, DTR, dtb, DI, DTR, b_dt, 0);
    // 6.5) convert W_out to bf16
    cvt_bf16_kernel<<<(DM * DI + 255) / 256, 256>>>(W_out, Wout_bf, DM * DI);
    // 7) scan (16 lanes/pair, PF=8)
    scan_kernel<<<(Bsz * DI) / 16, 256>>>(A_log, Dw);
    // 8) GEMM out (bf16): out = y @ W_out^T, transpose + residual
    gemm_bf16<2><<<dim3(DM / 128, MROWS / 128), 128, GSMEM_BF>>>(
        y_bf, DI, Wout_bf, DI, out, 0, DI, x);
}

// round 15
// speedup vs baseline: 1.1221x; 1.1221x over previous
#include <cuda_runtime.h>
#include <cuda_bf16.h>
#include <cstdint>

// ---------------------------------------------------------------------------
// MambaBlock: B=4, L=1024, D_MODEL=768, D_INNER=1536, D_STATE=16, DT_RANK=48
// Big GEMMs: mma.sync.m16n8k16.bf16.  Small GEMMs: tf32.
// Scan: 4 lanes per (b,d), 4 states/lane, PF=8 prefetch ring.
// xproj: split-K x6 + reduce.
// ---------------------------------------------------------------------------

#define Bsz 4
#define Lsz 1024
#define DM  768
#define DI  1536
#define DS  16
#define DTR 48
#define MROWS (Bsz * Lsz)   // 4096
#define SPLITK 6
#define XPK (DI / SPLITK)   // 256

__device__ __align__(16) __nv_bfloat16 g_hn_bf [MROWS * DM];
__device__ __align__(16) __nv_bfloat16 g_Win_bf[2 * DI * DM];
__device__ __align__(16) __nv_bfloat16 g_Wout_bf[DM * DI];
__device__ __align__(16) __nv_bfloat16 g_y_bf  [MROWS * DI];
__device__ __align__(16) float g_xz  [MROWS * 2 * DI];
__device__ __align__(16) float g_xssm[MROWS * DI];
__device__ __align__(16) float g_xdbl[MROWS * 80];
__device__ __align__(16) float g_xdbl_part[SPLITK * MROWS * 80];
__device__ __align__(16) float g_dt  [MROWS * DI];
__device__ __align__(16) float g_stats[MROWS * 2];

// ---------------------------------------------------------------------------
// fp32 -> bf16 conversion (weights)
// ---------------------------------------------------------------------------
__global__ void cvt_bf16_kernel(const float* __restrict__ src,
                                __nv_bfloat16* __restrict__ dst, int n)
{
    int i = blockIdx.x * blockDim.x + threadIdx.x;
    if (i < n) dst[i] = __float2bfloat16_rn(src[i]);
}

// ---------------------------------------------------------------------------
// 1) LayerNorm statistics
// ---------------------------------------------------------------------------
__global__ void ln_stats_kernel(const float* __restrict__ x)
{
    __shared__ float s_sum[256];
    __shared__ float s_sq[256];
    int tid  = threadIdx.x;
    int lid  = tid & 63;
    int part = tid >> 6;
    int b    = blockIdx.y;
    int l    = blockIdx.x * 64 + lid;
    const float* xb = x + (size_t)b * DM * Lsz + l;

    float sum = 0.f, sq = 0.f;
    int c0 = part * (DM / 4);
    #pragma unroll 8
    for (int c = c0; c < c0 + DM / 4; c++) {
        float v = xb[(size_t)c * Lsz];
        sum += v;
        sq  += v * v;
    }
    s_sum[tid] = sum;
    s_sq[tid]  = sq;
    __syncthreads();
    if (part == 0) {
        float ts = s_sum[tid] + s_sum[tid + 64] + s_sum[tid + 128] + s_sum[tid + 192];
        float tq = s_sq[tid]  + s_sq[tid + 64]  + s_sq[tid + 128]  + s_sq[tid + 192];
        float mu = ts / DM;
        float var = tq / DM - mu * mu;
        float rstd = rsqrtf(var + 1e-5f);
        int bl = b * Lsz + l;
        g_stats[bl * 2 + 0] = mu;
        g_stats[bl * 2 + 1] = rstd;
    }
}

// ---------------------------------------------------------------------------
// 2) Transpose (B,C,L)->(B*L,C) with LN applied; bf16 output.
// ---------------------------------------------------------------------------
__global__ void ln_apply_kernel(const float* __restrict__ x,
                                const float* __restrict__ gamma,
                                const float* __restrict__ beta)
{
    __shared__ float tile[32][33];
    int b  = blockIdx.z;
    int c0 = blockIdx.y * 32;
    int l0 = blockIdx.x * 32;
    const float* xb = x + (size_t)b * DM * Lsz;

    #pragma unroll
    for (int i0 = 0; i0 < 4; i0++) {
        int c = c0 + threadIdx.y + i0 * 8;
        tile[threadIdx.y + i0 * 8][threadIdx.x] = xb[(size_t)c * Lsz + l0 + threadIdx.x];
    }
    __syncthreads();
    #pragma unroll
    for (int i0 = 0; i0 < 4; i0++) {
        int l  = l0 + threadIdx.y + i0 * 8;
        int c  = c0 + threadIdx.x;
        int bl = b * Lsz + l;
        float mu   = g_stats[bl * 2 + 0];
        float rstd = g_stats[bl * 2 + 1];
        float v = tile[threadIdx.x][threadIdx.y + i0 * 8];
        g_hn_bf[(size_t)bl * DM + c] =
            __float2bfloat16_rn((v - mu) * rstd * gamma[c] + beta[c]);
    }
}

// ---------------------------------------------------------------------------
// mma + cp.async helpers
// ---------------------------------------------------------------------------
__device__ __forceinline__ void mma_tf32(float* c, const uint32_t* a, const uint32_t* b)
{
    asm volatile(
        "mma.sync.aligned.m16n8k8.row.col.f32.tf32.tf32.f32 "
        "{%0,%1,%2,%3}, {%4,%5,%6,%7}, {%8,%9}, {%0,%1,%2,%3};"
        : "+f"(c[0]), "+f"(c[1]), "+f"(c[2]), "+f"(c[3])
        : "r"(a[0]), "r"(a[1]), "r"(a[2]), "r"(a[3]), "r"(b[0]), "r"(b[1]));
}

__device__ __forceinline__ void mma_bf16(float* c, const uint32_t* a, const uint32_t* b)
{
    asm volatile(
        "mma.sync.aligned.m16n8k16.row.col.f32.bf16.bf16.f32 "
        "{%0,%1,%2,%3}, {%4,%5,%6,%7}, {%8,%9}, {%0,%1,%2,%3};"
        : "+f"(c[0]), "+f"(c[1]), "+f"(c[2]), "+f"(c[3])
        : "r"(a[0]), "r"(a[1]), "r"(a[2]), "r"(a[3]), "r"(b[0]), "r"(b[1]));
}

__device__ __forceinline__ void cp16(uint32_t dst_smem, const void* src)
{
    asm volatile("cp.async.cg.shared.global [%0], [%1], 16;"
                 :: "r"(dst_smem), "l"(src));
}
__device__ __forceinline__ void cp_commit()
{
    asm volatile("cp.async.commit_group;");
}
template<int N>
__device__ __forceinline__ void cp_wait()
{
    asm volatile("cp.async.wait_group %0;" :: "n"(N));
}

// ---------------------------------------------------------------------------
// bf16 tensor GEMM:  C[M,N] = A[M,K] * B[N,K]^T  (A,B bf16 row-major, C fp32)
// BM=BN=128, BK=32, 128 threads (2x2 warps, 64x64 tiles), 3-stage cp.async.
// EPI 0: plain coalesced store.  EPI 2: transpose store + residual.
// ---------------------------------------------------------------------------
template<int EPI>
__global__ void __launch_bounds__(128, 3)
gemm_bf16(const __nv_bfloat16* __restrict__ A, int lda,
          const __nv_bfloat16* __restrict__ B, int ldb,
          float* __restrict__ C, int ldc,
          int K, const float* __restrict__ xres)
{
    constexpr int NTH = 128;
    constexpr int BM = 128;
    constexpr int MT = 4, NT = 8;       // 64x64 warp tile
    constexpr int LDT = 20;             // words per row (16 data + 4 pad)
    constexpr int ST  = 3;
    constexpr int STG = BM * LDT;       // words per stage per matrix

    extern __shared__ uint32_t smem[];
    uint32_t* Asm = smem;
    uint32_t* Bsm = smem + ST * STG;

    const int tid   = threadIdx.x;
    const int warp  = tid >> 5;
    const int lane  = tid & 31;
    const int g     = lane >> 2;
    const int t     = lane & 3;

    const int wm0 = (warp >> 1) * 64;
    const int wn0 = (warp & 1) * 64;

    const int m0 = blockIdx.y * BM;
    const int n0 = blockIdx.x * BM;

    const int niter = K / 32;

    float acc[MT][NT][4];
    #pragma unroll
    for (int i = 0; i < MT; i++)
        #pragma unroll
        for (int j = 0; j < NT; j++)
            #pragma unroll
            for (int q = 0; q < 4; q++) acc[i][j][q] = 0.f;

    uint32_t sA = (uint32_t)__cvta_generic_to_shared(Asm);
    uint32_t sB = (uint32_t)__cvta_generic_to_shared(Bsm);

    auto issue = [&](int s, int it) {
        int k0 = it * 32;
        uint32_t baseA = sA + (uint32_t)s * (STG * 4);
        uint32_t baseB = sB + (uint32_t)s * (STG * 4);
        #pragma unroll
        for (int i = 0; i < 512 / NTH; i++) {
            int id = tid + NTH * i;
            int r  = id >> 2;
            int c  = id & 3;
            cp16(baseA + (uint32_t)(r * LDT + c * 4) * 4,
                 &A[(size_t)(m0 + r) * lda + k0 + c * 8]);
            cp16(baseB + (uint32_t)(r * LDT + c * 4) * 4,
                 &B[(size_t)(n0 + r) * ldb + k0 + c * 8]);
        }
    };

    issue(0, 0); cp_commit();
    issue(1, 1); cp_commit();

    for (int it = 0; it < niter; it++) {
        const int s = it % ST;
        cp_wait<1>();
        __syncthreads();

        if (it + 2 < niter) issue((it + 2) % ST, it + 2);
        cp_commit();

        const uint32_t* as = Asm + s * STG;
        const uint32_t* bs = Bsm + s * STG;
        #pragma unroll
        for (int ks = 0; ks < 2; ks++) {
            const int kk = ks * 8;
            uint32_t afr[MT][4];
            uint32_t bfr[NT][2];
            #pragma unroll
            for (int i = 0; i < MT; i++) {
                int base = wm0 + 16 * i;
                afr[i][0] = as[(base + g)     * LDT + kk + t];
                afr[i][1] = as[(base + g + 8) * LDT + kk + t];
                afr[i][2] = as[(base + g)     * LDT + kk + 4 + t];
                afr[i][3] = as[(base + g + 8) * LDT + kk + 4 + t];
            }
            #pragma unroll
            for (int j = 0; j < NT; j++) {
                int bb = wn0 + 8 * j;
                bfr[j][0] = bs[(bb + g) * LDT + kk + t];
                bfr[j][1] = bs[(bb + g) * LDT + kk + 4 + t];
            }
            #pragma unroll
            for (int i = 0; i < MT; i++)
                #pragma unroll
                for (int j = 0; j < NT; j++)
                    mma_bf16(acc[i][j], afr[i], bfr[j]);
        }
    }

    #pragma unroll
    for (int i = 0; i < MT; i++) {
        int r0 = m0 + wm0 + 16 * i + g;
        int r1 = r0 + 8;
        #pragma unroll
        for (int j = 0; j < NT; j++) {
            int col = n0 + wn0 + 8 * j + 2 * t;
            float c0 = acc[i][j][0], c1 = acc[i][j][1];
            float c2 = acc[i][j][2], c3 = acc[i][j][3];
            if (EPI == 2) {
                int b0i = r0 >> 10, l0i = r0 & 1023;
                int b1i = r1 >> 10, l1i = r1 & 1023;
                size_t o00 = ((size_t)(b0i * DM + col))     * Lsz + l0i;
                size_t o01 = ((size_t)(b0i * DM + col + 1)) * Lsz + l0i;
                size_t o10 = ((size_t)(b1i * DM + col))     * Lsz + l1i;
                size_t o11 = ((size_t)(b1i * DM + col + 1)) * Lsz + l1i;
                C[o00] = c0 + xres[o00];
                C[o01] = c1 + xres[o01];
                C[o10] = c2 + xres[o10];
                C[o11] = c3 + xres[o11];
            } else {
                *reinterpret_cast<float2*>(&C[(size_t)r0 * ldc + col]) = make_float2(c0, c1);
                *reinterpret_cast<float2*>(&C[(size_t)r1 * ldc + col]) = make_float2(c2, c3);
            }
        }
    }
}

// ---------------------------------------------------------------------------
// tf32 tensor GEMM (small GEMMs: xproj split-K, dt).
// ---------------------------------------------------------------------------
template<int BN, int WARPS_M, int WARPS_N, int EPI>
__global__ void __launch_bounds__(32 * WARPS_M * WARPS_N, 3)
gemm_tf32(const float* __restrict__ A, int lda,
          const float* __restrict__ B, int ldb,
          float* __restrict__ C, int ldc,
          int K,
          const float* __restrict__ bias,
          int split_stride)
{
    constexpr int NTH = 32 * WARPS_M * WARPS_N;
    constexpr int BM = 128;
    constexpr int WM = BM / WARPS_M;
    constexpr int WN = BN / WARPS_N;
    constexpr int MT = WM / 16;
    constexpr int NT = WN / 8;
    constexpr int LDT = 20;
    constexpr int NA4 = BM * 4;
    constexpr int NB4 = BN * 4;
    constexpr int ST  = 3;
    constexpr int ASTG = BM * LDT;
    constexpr int BSTG = BN * LDT;

    extern __shared__ uint32_t smem[];
    uint32_t* Asm = smem;
    uint32_t* Bsm = smem + ST * ASTG;

    const int tid   = threadIdx.x;
    const int warp  = tid >> 5;
    const int lane  = tid & 31;
    const int g     = lane >> 2;
    const int t     = lane & 3;

    const int warp_m = warp / WARPS_N;
    const int warp_n = warp % WARPS_N;
    const int wm0 = warp_m * WM;
    const int wn0 = warp_n * WN;

    const int m0 = blockIdx.y * BM;
    const int n0 = blockIdx.x * BN;

    const float* Ae = A + (size_t)blockIdx.z * K;
    const float* Be = B + (size_t)blockIdx.z * K;
    float* Ce = C + (size_t)blockIdx.z * split_stride;

    const int niter = K / 16;

    float acc[MT][NT][4];
    #pragma unroll
    for (int i = 0; i < MT; i++)
        #pragma unroll
        for (int j = 0; j < NT; j++)
            #pragma unroll
            for (int q = 0; q < 4; q++) acc[i][j][q] = 0.f;

    uint32_t sA = (uint32_t)__cvta_generic_to_shared(Asm);
    uint32_t sB = (uint32_t)__cvta_generic_to_shared(Bsm);

    auto issue = [&](int s, int it) {
        int k0 = it * 16;
        uint32_t baseA = sA + (uint32_t)s * (ASTG * 4);
        #pragma unroll
        for (int i = 0; i < NA4 / NTH; i++) {
            int id = tid + NTH * i;
            int r  = id >> 2;
            int kq = (id & 3) * 4;
            cp16(baseA + (uint32_t)(r * LDT + kq) * 4,
                 &Ae[(size_t)(m0 + r) * lda + k0 + kq]);
        }
        uint32_t baseB = sB + (uint32_t)s * (BSTG * 4);
        #pragma unroll
        for (int i = 0; i < (NB4 + NTH - 1) / NTH; i++) {
            int id = tid + NTH * i;
            if (id < NB4) {
                int r  = id >> 2;
                int kq = (id & 3) * 4;
                cp16(baseB + (uint32_t)(r * LDT + kq) * 4,
                     &Be[(size_t)(n0 + r) * ldb + k0 + kq]);
            }
        }
    };

    issue(0, 0); cp_commit();
    issue(1, 1); cp_commit();

    for (int it = 0; it < niter; it++) {
        const int s = it % ST;
        cp_wait<1>();
        __syncthreads();

        if (it + 2 < niter) issue((it + 2) % ST, it + 2);
        cp_commit();

        const uint32_t* as = Asm + s * ASTG;
        const uint32_t* bs = Bsm + s * BSTG;
        #pragma unroll
        for (int ks = 0; ks < 2; ks++) {
            const int kk = ks * 8;
            uint32_t afr[MT][4];
            uint32_t bfr[NT][2];
            #pragma unroll
            for (int i = 0; i < MT; i++) {
                int base = wm0 + 16 * i;
                afr[i][0] = as[(base + g)     * LDT + kk + t];
                afr[i][1] = as[(base + g + 8) * LDT + kk + t];
                afr[i][2] = as[(base + g)     * LDT + kk + t + 4];
                afr[i][3] = as[(base + g + 8) * LDT + kk + t + 4];
            }
            #pragma unroll
            for (int j = 0; j < NT; j++) {
                int bb = wn0 + 8 * j;
                bfr[j][0] = bs[(bb + g) * LDT + kk + t];
                bfr[j][1] = bs[(bb + g) * LDT + kk + t + 4];
            }
            #pragma unroll
            for (int i = 0; i < MT; i++)
                #pragma unroll
                for (int j = 0; j < NT; j++)
                    mma_tf32(acc[i][j], afr[i], bfr[j]);
        }
    }

    #pragma unroll
    for (int i = 0; i < MT; i++) {
        int r0 = m0 + wm0 + 16 * i + g;
        int r1 = r0 + 8;
        #pragma unroll
        for (int j = 0; j < NT; j++) {
            int col = n0 + wn0 + 8 * j + 2 * t;
            float c0 = acc[i][j][0], c1 = acc[i][j][1];
            float c2 = acc[i][j][2], c3 = acc[i][j][3];
            if (EPI == 1) {
                float b0 = bias[col], b1 = bias[col + 1];
                c0 += b0; c1 += b1; c2 += b0; c3 += b1;
                c0 = (c0 > 20.f) ? c0 : log1pf(expf(c0));
                c1 = (c1 > 20.f) ? c1 : log1pf(expf(c1));
                c2 = (c2 > 20.f) ? c2 : log1pf(expf(c2));
                c3 = (c3 > 20.f) ? c3 : log1pf(expf(c3));
            }
            *reinterpret_cast<float2*>(&Ce[(size_t)r0 * ldc + col]) = make_float2(c0, c1);
            *reinterpret_cast<float2*>(&Ce[(size_t)r1 * ldc + col]) = make_float2(c2, c3);
        }
    }
}

#define GSMEM(BN) (3 * (128 + (BN)) * 20 * 4)
#define GSMEM_BF  (3 * 2 * 128 * 20 * 4)

// reduce the SPLITK partial xproj results -> g_xdbl (deterministic order)
__global__ void xdbl_reduce_kernel()
{
    int idx = blockIdx.x * blockDim.x + threadIdx.x;
    if (idx >= MROWS * 80) return;
    float s = 0.f;
    #pragma unroll
    for (int p = 0; p < SPLITK; p++)
        s += g_xdbl_part[(size_t)p * (MROWS * 80) + idx];
    g_xdbl[idx] = s;
}

// ---------------------------------------------------------------------------
// 4) depthwise causal conv(4) + bias + silu
// ---------------------------------------------------------------------------
__global__ void conv_silu_kernel(const float* __restrict__ conv_w,
                                 const float* __restrict__ conv_b)
{
    int idx = blockIdx.x * blockDim.x + threadIdx.x;
    if (idx >= MROWS * DI) return;
    int d  = idx % DI;
    int bl = idx / DI;
    int l  = bl & (Lsz - 1);

    float acc = conv_b[d];
    #pragma unroll
    for (int j = 0; j < 4; j++) {
        int ll = l - 3 + j;
        if (ll >= 0)
            acc += conv_w[d * 4 + j] * g_xz[(size_t)(bl - 3 + j) * (2 * DI) + d];
    }
    g_xssm[idx] = acc / (1.f + expf(-acc));
}

// ---------------------------------------------------------------------------
// 7) selective scan: 4 lanes per (b,d), 4 states/lane, PF=8 prefetch ring.
// ---------------------------------------------------------------------------
#define PF 8

__global__ void __launch_bounds__(128)
scan_kernel(const float* __restrict__ A_log,
            const float* __restrict__ Dw)
{
    int pair = blockIdx.x * (blockDim.x >> 2) + (threadIdx.x >> 2);
    if (pair >= Bsz * DI) return;
    int ln = threadIdx.x & 3;
    int b = pair / DI;
    int d = pair % DI;
    int n0 = ln * 4;

    float Av[4], h[4];
    #pragma unroll
    for (int j = 0; j < 4; j++) {
        Av[j] = -expf(A_log[d * DS + n0 + j]);
        h[j] = 0.f;
    }
    float Dd = Dw[d];

    const float* dtp = g_dt   + (size_t)b * Lsz * DI + d;
    const float* xp  = g_xssm + (size_t)b * Lsz * DI + d;
    const float* dbl = g_xdbl + (size_t)b * Lsz * 80;
    const float* zp  = g_xz   + (size_t)b * Lsz * (2 * DI) + DI + d;
    __nv_bfloat16* yp = g_y_bf + (size_t)b * Lsz * DI + d;

    float  pdt[PF], px[PF], pz[PF];
    float4 pB[PF], pC[PF];

    #pragma unroll
    for (int j = 0; j < PF; j++) {
        pdt[j] = dtp[(size_t)j * DI];
        px[j]  = xp [(size_t)j * DI];
        pB[j]  = *reinterpret_cast<const float4*>(&dbl[j * 80 + DTR + n0]);
        pC[j]  = *reinterpret_cast<const float4*>(&dbl[j * 80 + DTR + DS + n0]);
        pz[j]  = zp[(size_t)j * (2 * DI)];
    }

    for (int l0 = 0; l0 < Lsz; l0 += PF) {
        #pragma unroll
        for (int j = 0; j < PF; j++) {
            const int l = l0 + j;
            float  dt_t = pdt[j];
            float  x_t  = px[j];
            float4 Bv   = pB[j];
            float4 Cv   = pC[j];
            float  zv   = pz[j];
            const int lf = l + PF;
            if (lf < Lsz) {
                pdt[j] = dtp[(size_t)lf * DI];
                px[j]  = xp [(size_t)lf * DI];
                pB[j]  = *reinterpret_cast<const float4*>(&dbl[lf * 80 + DTR + n0]);
                pC[j]  = *reinterpret_cast<const float4*>(&dbl[lf * 80 + DTR + DS + n0]);
                pz[j]  = zp[(size_t)lf * (2 * DI)];
            }
            float dtx = dt_t * x_t;
            h[0] = expf(dt_t * Av[0]) * h[0] + dtx * Bv.x;
            h[1] = expf(dt_t * Av[1]) * h[1] + dtx * Bv.y;
            h[2] = expf(dt_t * Av[2]) * h[2] + dtx * Bv.z;
            h[3] = expf(dt_t * Av[3]) * h[3] + dtx * Bv.w;
            float part = h[0] * Cv.x + h[1] * Cv.y + h[2] * Cv.z + h[3] * Cv.w;
            part += __shfl_xor_sync(0xFFFFFFFFu, part, 2);
            part += __shfl_xor_sync(0xFFFFFFFFu, part, 1);
            if (ln == 0) {
                float sz = zv / (1.f + expf(-zv));
                yp[(size_t)l * DI] = __float2bfloat16_rn((part + Dd * x_t) * sz);
            }
        }
    }
}

// ---------------------------------------------------------------------------
extern "C" void kernel_launch(void* const* d_in, const int* in_sizes, int n_in,
                              void* d_out, int out_size)
{
    const float* x      = (const float*)d_in[0];
    const float* gamma  = (const float*)d_in[1];
    const float* beta   = (const float*)d_in[2];
    const float* W_in   = (const float*)d_in[3];
    const float* conv_w = (const float*)d_in[4];
    const float* conv_b = (const float*)d_in[5];
    const float* W_xproj= (const float*)d_in[6];
    const float* W_dt   = (const float*)d_in[7];
    const float* b_dt   = (const float*)d_in[8];
    const float* A_log  = (const float*)d_in[9];
    const float* Dw     = (const float*)d_in[10];
    const float* W_out  = (const float*)d_in[11];
    float* out = (float*)d_out;

    static float *xz = nullptr, *xssm = nullptr, *xdbl = nullptr,
                 *xdbl_part = nullptr, *dtb = nullptr;
    static __nv_bfloat16 *hn_bf = nullptr, *Win_bf = nullptr,
                         *Wout_bf = nullptr, *y_bf = nullptr;
    if (!xz) {
        cudaGetSymbolAddress((void**)&xz,        g_xz);
        cudaGetSymbolAddress((void**)&xssm,      g_xssm);
        cudaGetSymbolAddress((void**)&xdbl,      g_xdbl);
        cudaGetSymbolAddress((void**)&xdbl_part, g_xdbl_part);
        cudaGetSymbolAddress((void**)&dtb,       g_dt);
        cudaGetSymbolAddress((void**)&hn_bf,     g_hn_bf);
        cudaGetSymbolAddress((void**)&Win_bf,    g_Win_bf);
        cudaGetSymbolAddress((void**)&Wout_bf,   g_Wout_bf);
        cudaGetSymbolAddress((void**)&y_bf,      g_y_bf);
        cudaFuncSetAttribute(gemm_bf16<0>,
                             cudaFuncAttributeMaxDynamicSharedMemorySize, GSMEM_BF);
        cudaFuncSetAttribute(gemm_bf16<2>,
                             cudaFuncAttributeMaxDynamicSharedMemorySize, GSMEM_BF);
        cudaFuncSetAttribute(gemm_tf32<128, 2, 2, 1>,
                             cudaFuncAttributeMaxDynamicSharedMemorySize, GSMEM(128));
        cudaFuncSetAttribute(gemm_tf32<80, 4, 1, 0>,
                             cudaFuncAttributeMaxDynamicSharedMemorySize, GSMEM(80));
    }

    // 0) convert W_in to bf16 (keeps GEMM1 at profiled launch index 3)
    cvt_bf16_kernel<<<(2 * DI * DM + 255) / 256, 256>>>(W_in, Win_bf, 2 * DI * DM);
    // 1) LN stats
    ln_stats_kernel<<<dim3(Lsz / 64, Bsz), 256>>>(x);
    // 2) transpose + LN apply (bf16 out)
    ln_apply_kernel<<<dim3(Lsz / 32, DM / 32, Bsz), dim3(32, 8)>>>(x, gamma, beta);
    // 3) GEMM1 (bf16): xz = hn @ W_in^T   (4096 x 3072 x 768)
    gemm_bf16<0><<<dim3(3072 / 128, MROWS / 128), 128, GSMEM_BF>>>(
        hn_bf, DM, Win_bf, DM, xz, 2 * DI, DM, nullptr);
    // 4) conv + silu
    conv_silu_kernel<<<(MROWS * DI + 255) / 256, 256>>>(conv_w, conv_b);
    // 5) xproj split-K x6 + reduce
    gemm_tf32<80, 4, 1, 0><<<dim3(1, MROWS / 128, SPLITK), 128, GSMEM(80)>>>(
        xssm, DI, W_xproj, DI, xdbl_part, 80, XPK, nullptr, MROWS * 80);
    xdbl_reduce_kernel<<<(MROWS * 80 + 255) / 256, 256>>>();
    // 6) dt = softplus(xdbl[:, :48] @ W_dt^T + b_dt)
    gemm_tf32<128, 2, 2, 1><<<dim3(DI / 128, MROWS / 128), 128, GSMEM(128)>>>(
        xdbl, 80, W_dt, DTR, dtb, DI, DTR, b_dt, 0);
    // 6.5) convert W_out to bf16
    cvt_bf16_kernel<<<(DM * DI + 255) / 256, 256>>>(W_out, Wout_bf, DM * DI);
    // 7) scan (4 lanes/pair, PF=8)
    scan_kernel<<<(Bsz * DI * 4 + 127) / 128, 128>>>(A_log, Dw);
    // 8) GEMM out (bf16): out = y @ W_out^T, transpose + residual
    gemm_bf16<2><<<dim3(DM / 128, MROWS / 128), 128, GSMEM_BF>>>(
        y_bf, DI, Wout_bf, DI, out, 0, DI, x);
}

// round 17
// speedup vs baseline: 1.2734x; 1.1348x over previous
#include <cuda_runtime.h>
#include <cuda_bf16.h>
#include <cstdint>

// ---------------------------------------------------------------------------
// MambaBlock: B=4, L=1024, D_MODEL=768, D_INNER=1536, D_STATE=16, DT_RANK=48
// Big GEMMs: mma.sync.m16n8k16.bf16.  Small GEMMs: tf32.
// Scan: 3-pass chunked parallel scan (8 chunks of 128; 8x L-parallelism).
// xproj: split-K x6 + reduce.
// ---------------------------------------------------------------------------

#define Bsz 4
#define Lsz 1024
#define DM  768
#define DI  1536
#define DS  16
#define DTR 48
#define MROWS (Bsz * Lsz)   // 4096
#define SPLITK 6
#define XPK (DI / SPLITK)   // 256
#define NCH 8               // scan chunks
#define CL  (Lsz / NCH)     // 128 steps per chunk
#define NPAIR (Bsz * DI)    // 6144

__device__ __align__(16) __nv_bfloat16 g_hn_bf [MROWS * DM];
__device__ __align__(16) __nv_bfloat16 g_Win_bf[2 * DI * DM];
__device__ __align__(16) __nv_bfloat16 g_Wout_bf[DM * DI];
__device__ __align__(16) __nv_bfloat16 g_y_bf  [MROWS * DI];
__device__ __align__(16) float g_xz  [MROWS * 2 * DI];
__device__ __align__(16) float g_xssm[MROWS * DI];
__device__ __align__(16) float g_xdbl[MROWS * 80];
__device__ __align__(16) float g_xdbl_part[SPLITK * MROWS * 80];
__device__ __align__(16) float g_dt  [MROWS * DI];
__device__ __align__(16) float g_stats[MROWS * 2];
// chunked-scan state: [pair][chunk][state]
__device__ __align__(16) float g_hend  [NPAIR * NCH * DS];
__device__ __align__(16) float g_Pprod [NPAIR * NCH * DS];
__device__ __align__(16) float g_hstart[NPAIR * NCH * DS];

// ---------------------------------------------------------------------------
__global__ void cvt_bf16_kernel(const float* __restrict__ src,
                                __nv_bfloat16* __restrict__ dst, int n)
{
    int i = blockIdx.x * blockDim.x + threadIdx.x;
    if (i < n) dst[i] = __float2bfloat16_rn(src[i]);
}

// ---------------------------------------------------------------------------
// 1) LayerNorm statistics
// ---------------------------------------------------------------------------
__global__ void ln_stats_kernel(const float* __restrict__ x)
{
    __shared__ float s_sum[256];
    __shared__ float s_sq[256];
    int tid  = threadIdx.x;
    int lid  = tid & 63;
    int part = tid >> 6;
    int b    = blockIdx.y;
    int l    = blockIdx.x * 64 + lid;
    const float* xb = x + (size_t)b * DM * Lsz + l;

    float sum = 0.f, sq = 0.f;
    int c0 = part * (DM / 4);
    #pragma unroll 8
    for (int c = c0; c < c0 + DM / 4; c++) {
        float v = xb[(size_t)c * Lsz];
        sum += v;
        sq  += v * v;
    }
    s_sum[tid] = sum;
    s_sq[tid]  = sq;
    __syncthreads();
    if (part == 0) {
        float ts = s_sum[tid] + s_sum[tid + 64] + s_sum[tid + 128] + s_sum[tid + 192];
        float tq = s_sq[tid]  + s_sq[tid + 64]  + s_sq[tid + 128]  + s_sq[tid + 192];
        float mu = ts / DM;
        float var = tq / DM - mu * mu;
        float rstd = rsqrtf(var + 1e-5f);
        int bl = b * Lsz + l;
        g_stats[bl * 2 + 0] = mu;
        g_stats[bl * 2 + 1] = rstd;
    }
}

// ---------------------------------------------------------------------------
// 2) Transpose (B,C,L)->(B*L,C) with LN applied; bf16 output.
// ---------------------------------------------------------------------------
__global__ void ln_apply_kernel(const float* __restrict__ x,
                                const float* __restrict__ gamma,
                                const float* __restrict__ beta)
{
    __shared__ float tile[32][33];
    int b  = blockIdx.z;
    int c0 = blockIdx.y * 32;
    int l0 = blockIdx.x * 32;
    const float* xb = x + (size_t)b * DM * Lsz;

    #pragma unroll
    for (int i0 = 0; i0 < 4; i0++) {
        int c = c0 + threadIdx.y + i0 * 8;
        tile[threadIdx.y + i0 * 8][threadIdx.x] = xb[(size_t)c * Lsz + l0 + threadIdx.x];
    }
    __syncthreads();
    #pragma unroll
    for (int i0 = 0; i0 < 4; i0++) {
        int l  = l0 + threadIdx.y + i0 * 8;
        int c  = c0 + threadIdx.x;
        int bl = b * Lsz + l;
        float mu   = g_stats[bl * 2 + 0];
        float rstd = g_stats[bl * 2 + 1];
        float v = tile[threadIdx.x][threadIdx.y + i0 * 8];
        g_hn_bf[(size_t)bl * DM + c] =
            __float2bfloat16_rn((v - mu) * rstd * gamma[c] + beta[c]);
    }
}

// ---------------------------------------------------------------------------
// mma + cp.async helpers
// ---------------------------------------------------------------------------
__device__ __forceinline__ void mma_tf32(float* c, const uint32_t* a, const uint32_t* b)
{
    asm volatile(
        "mma.sync.aligned.m16n8k8.row.col.f32.tf32.tf32.f32 "
        "{%0,%1,%2,%3}, {%4,%5,%6,%7}, {%8,%9}, {%0,%1,%2,%3};"
        : "+f"(c[0]), "+f"(c[1]), "+f"(c[2]), "+f"(c[3])
        : "r"(a[0]), "r"(a[1]), "r"(a[2]), "r"(a[3]), "r"(b[0]), "r"(b[1]));
}

__device__ __forceinline__ void mma_bf16(float* c, const uint32_t* a, const uint32_t* b)
{
    asm volatile(
        "mma.sync.aligned.m16n8k16.row.col.f32.bf16.bf16.f32 "
        "{%0,%1,%2,%3}, {%4,%5,%6,%7}, {%8,%9}, {%0,%1,%2,%3};"
        : "+f"(c[0]), "+f"(c[1]), "+f"(c[2]), "+f"(c[3])
        : "r"(a[0]), "r"(a[1]), "r"(a[2]), "r"(a[3]), "r"(b[0]), "r"(b[1]));
}

__device__ __forceinline__ void cp16(uint32_t dst_smem, const void* src)
{
    asm volatile("cp.async.cg.shared.global [%0], [%1], 16;"
                 :: "r"(dst_smem), "l"(src));
}
__device__ __forceinline__ void cp_commit()
{
    asm volatile("cp.async.commit_group;");
}
template<int N>
__device__ __forceinline__ void cp_wait()
{
    asm volatile("cp.async.wait_group %0;" :: "n"(N));
}

// ---------------------------------------------------------------------------
// bf16 tensor GEMM (unchanged from R15)
// ---------------------------------------------------------------------------
template<int EPI>
__global__ void __launch_bounds__(128, 3)
gemm_bf16(const __nv_bfloat16* __restrict__ A, int lda,
          const __nv_bfloat16* __restrict__ B, int ldb,
          float* __restrict__ C, int ldc,
          int K, const float* __restrict__ xres)
{
    constexpr int NTH = 128;
    constexpr int BM = 128;
    constexpr int MT = 4, NT = 8;
    constexpr int LDT = 20;
    constexpr int ST  = 3;
    constexpr int STG = BM * LDT;

    extern __shared__ uint32_t smem[];
    uint32_t* Asm = smem;
    uint32_t* Bsm = smem + ST * STG;

    const int tid   = threadIdx.x;
    const int warp  = tid >> 5;
    const int lane  = tid & 31;
    const int g     = lane >> 2;
    const int t     = lane & 3;

    const int wm0 = (warp >> 1) * 64;
    const int wn0 = (warp & 1) * 64;

    const int m0 = blockIdx.y * BM;
    const int n0 = blockIdx.x * BM;

    const int niter = K / 32;

    float acc[MT][NT][4];
    #pragma unroll
    for (int i = 0; i < MT; i++)
        #pragma unroll
        for (int j = 0; j < NT; j++)
            #pragma unroll
            for (int q = 0; q < 4; q++) acc[i][j][q] = 0.f;

    uint32_t sA = (uint32_t)__cvta_generic_to_shared(Asm);
    uint32_t sB = (uint32_t)__cvta_generic_to_shared(Bsm);

    auto issue = [&](int s, int it) {
        int k0 = it * 32;
        uint32_t baseA = sA + (uint32_t)s * (STG * 4);
        uint32_t baseB = sB + (uint32_t)s * (STG * 4);
        #pragma unroll
        for (int i = 0; i < 512 / NTH; i++) {
            int id = tid + NTH * i;
            int r  = id >> 2;
            int c  = id & 3;
            cp16(baseA + (uint32_t)(r * LDT + c * 4) * 4,
                 &A[(size_t)(m0 + r) * lda + k0 + c * 8]);
            cp16(baseB + (uint32_t)(r * LDT + c * 4) * 4,
                 &B[(size_t)(n0 + r) * ldb + k0 + c * 8]);
        }
    };

    issue(0, 0); cp_commit();
    issue(1, 1); cp_commit();

    for (int it = 0; it < niter; it++) {
        const int s = it % ST;
        cp_wait<1>();
        __syncthreads();

        if (it + 2 < niter) issue((it + 2) % ST, it + 2);
        cp_commit();

        const uint32_t* as = Asm + s * STG;
        const uint32_t* bs = Bsm + s * STG;
        #pragma unroll
        for (int ks = 0; ks < 2; ks++) {
            const int kk = ks * 8;
            uint32_t afr[MT][4];
            uint32_t bfr[NT][2];
            #pragma unroll
            for (int i = 0; i < MT; i++) {
                int base = wm0 + 16 * i;
                afr[i][0] = as[(base + g)     * LDT + kk + t];
                afr[i][1] = as[(base + g + 8) * LDT + kk + t];
                afr[i][2] = as[(base + g)     * LDT + kk + 4 + t];
                afr[i][3] = as[(base + g + 8) * LDT + kk + 4 + t];
            }
            #pragma unroll
            for (int j = 0; j < NT; j++) {
                int bb = wn0 + 8 * j;
                bfr[j][0] = bs[(bb + g) * LDT + kk + t];
                bfr[j][1] = bs[(bb + g) * LDT + kk + 4 + t];
            }
            #pragma unroll
            for (int i = 0; i < MT; i++)
                #pragma unroll
                for (int j = 0; j < NT; j++)
                    mma_bf16(acc[i][j], afr[i], bfr[j]);
        }
    }

    #pragma unroll
    for (int i = 0; i < MT; i++) {
        int r0 = m0 + wm0 + 16 * i + g;
        int r1 = r0 + 8;
        #pragma unroll
        for (int j = 0; j < NT; j++) {
            int col = n0 + wn0 + 8 * j + 2 * t;
            float c0 = acc[i][j][0], c1 = acc[i][j][1];
            float c2 = acc[i][j][2], c3 = acc[i][j][3];
            if (EPI == 2) {
                int b0i = r0 >> 10, l0i = r0 & 1023;
                int b1i = r1 >> 10, l1i = r1 & 1023;
                size_t o00 = ((size_t)(b0i * DM + col))     * Lsz + l0i;
                size_t o01 = ((size_t)(b0i * DM + col + 1)) * Lsz + l0i;
                size_t o10 = ((size_t)(b1i * DM + col))     * Lsz + l1i;
                size_t o11 = ((size_t)(b1i * DM + col + 1)) * Lsz + l1i;
                C[o00] = c0 + xres[o00];
                C[o01] = c1 + xres[o01];
                C[o10] = c2 + xres[o10];
                C[o11] = c3 + xres[o11];
            } else {
                *reinterpret_cast<float2*>(&C[(size_t)r0 * ldc + col]) = make_float2(c0, c1);
                *reinterpret_cast<float2*>(&C[(size_t)r1 * ldc + col]) = make_float2(c2, c3);
            }
        }
    }
}

// ---------------------------------------------------------------------------
// tf32 tensor GEMM (small GEMMs: xproj split-K, dt) - unchanged
// ---------------------------------------------------------------------------
template<int BN, int WARPS_M, int WARPS_N, int EPI>
__global__ void __launch_bounds__(32 * WARPS_M * WARPS_N, 3)
gemm_tf32(const float* __restrict__ A, int lda,
          const float* __restrict__ B, int ldb,
          float* __restrict__ C, int ldc,
          int K,
          const float* __restrict__ bias,
          int split_stride)
{
    constexpr int NTH = 32 * WARPS_M * WARPS_N;
    constexpr int BM = 128;
    constexpr int WM = BM / WARPS_M;
    constexpr int WN = BN / WARPS_N;
    constexpr int MT = WM / 16;
    constexpr int NT = WN / 8;
    constexpr int LDT = 20;
    constexpr int NA4 = BM * 4;
    constexpr int NB4 = BN * 4;
    constexpr int ST  = 3;
    constexpr int ASTG = BM * LDT;
    constexpr int BSTG = BN * LDT;

    extern __shared__ uint32_t smem[];
    uint32_t* Asm = smem;
    uint32_t* Bsm = smem + ST * ASTG;

    const int tid   = threadIdx.x;
    const int warp  = tid >> 5;
    const int lane  = tid & 31;
    const int g     = lane >> 2;
    const int t     = lane & 3;

    const int warp_m = warp / WARPS_N;
    const int warp_n = warp % WARPS_N;
    const int wm0 = warp_m * WM;
    const int wn0 = warp_n * WN;

    const int m0 = blockIdx.y * BM;
    const int n0 = blockIdx.x * BN;

    const float* Ae = A + (size_t)blockIdx.z * K;
    const float* Be = B + (size_t)blockIdx.z * K;
    float* Ce = C + (size_t)blockIdx.z * split_stride;

    const int niter = K / 16;

    float acc[MT][NT][4];
    #pragma unroll
    for (int i = 0; i < MT; i++)
        #pragma unroll
        for (int j = 0; j < NT; j++)
            #pragma unroll
            for (int q = 0; q < 4; q++) acc[i][j][q] = 0.f;

    uint32_t sA = (uint32_t)__cvta_generic_to_shared(Asm);
    uint32_t sB = (uint32_t)__cvta_generic_to_shared(Bsm);

    auto issue = [&](int s, int it) {
        int k0 = it * 16;
        uint32_t baseA = sA + (uint32_t)s * (ASTG * 4);
        #pragma unroll
        for (int i = 0; i < NA4 / NTH; i++) {
            int id = tid + NTH * i;
            int r  = id >> 2;
            int kq = (id & 3) * 4;
            cp16(baseA + (uint32_t)(r * LDT + kq) * 4,
                 &Ae[(size_t)(m0 + r) * lda + k0 + kq]);
        }
        uint32_t baseB = sB + (uint32_t)s * (BSTG * 4);
        #pragma unroll
        for (int i = 0; i < (NB4 + NTH - 1) / NTH; i++) {
            int id = tid + NTH * i;
            if (id < NB4) {
                int r  = id >> 2;
                int kq = (id & 3) * 4;
                cp16(baseB + (uint32_t)(r * LDT + kq) * 4,
                     &Be[(size_t)(n0 + r) * ldb + k0 + kq]);
            }
        }
    };

    issue(0, 0); cp_commit();
    issue(1, 1); cp_commit();

    for (int it = 0; it < niter; it++) {
        const int s = it % ST;
        cp_wait<1>();
        __syncthreads();

        if (it + 2 < niter) issue((it + 2) % ST, it + 2);
        cp_commit();

        const uint32_t* as = Asm + s * ASTG;
        const uint32_t* bs = Bsm + s * BSTG;
        #pragma unroll
        for (int ks = 0; ks < 2; ks++) {
            const int kk = ks * 8;
            uint32_t afr[MT][4];
            uint32_t bfr[NT][2];
            #pragma unroll
            for (int i = 0; i < MT; i++) {
                int base = wm0 + 16 * i;
                afr[i][0] = as[(base + g)     * LDT + kk + t];
                afr[i][1] = as[(base + g + 8) * LDT + kk + t];
                afr[i][2] = as[(base + g)     * LDT + kk + t + 4];
                afr[i][3] = as[(base + g + 8) * LDT + kk + t + 4];
            }
            #pragma unroll
            for (int j = 0; j < NT; j++) {
                int bb = wn0 + 8 * j;
                bfr[j][0] = bs[(bb + g) * LDT + kk + t];
                bfr[j][1] = bs[(bb + g) * LDT + kk + t + 4];
            }
            #pragma unroll
            for (int i = 0; i < MT; i++)
                #pragma unroll
                for (int j = 0; j < NT; j++)
                    mma_tf32(acc[i][j], afr[i], bfr[j]);
        }
    }

    #pragma unroll
    for (int i = 0; i < MT; i++) {
        int r0 = m0 + wm0 + 16 * i + g;
        int r1 = r0 + 8;
        #pragma unroll
        for (int j = 0; j < NT; j++) {
            int col = n0 + wn0 + 8 * j + 2 * t;
            float c0 = acc[i][j][0], c1 = acc[i][j][1];
            float c2 = acc[i][j][2], c3 = acc[i][j][3];
            if (EPI == 1) {
                float b0 = bias[col], b1 = bias[col + 1];
                c0 += b0; c1 += b1; c2 += b0; c3 += b1;
                c0 = (c0 > 20.f) ? c0 : log1pf(expf(c0));
                c1 = (c1 > 20.f) ? c1 : log1pf(expf(c1));
                c2 = (c2 > 20.f) ? c2 : log1pf(expf(c2));
                c3 = (c3 > 20.f) ? c3 : log1pf(expf(c3));
            }
            *reinterpret_cast<float2*>(&Ce[(size_t)r0 * ldc + col]) = make_float2(c0, c1);
            *reinterpret_cast<float2*>(&Ce[(size_t)r1 * ldc + col]) = make_float2(c2, c3);
        }
    }
}

#define GSMEM(BN) (3 * (128 + (BN)) * 20 * 4)
#define GSMEM_BF  (3 * 2 * 128 * 20 * 4)

__global__ void xdbl_reduce_kernel()
{
    int idx = blockIdx.x * blockDim.x + threadIdx.x;
    if (idx >= MROWS * 80) return;
    float s = 0.f;
    #pragma unroll
    for (int p = 0; p < SPLITK; p++)
        s += g_xdbl_part[(size_t)p * (MROWS * 80) + idx];
    g_xdbl[idx] = s;
}

// ---------------------------------------------------------------------------
// 4) depthwise causal conv(4) + bias + silu
// ---------------------------------------------------------------------------
__global__ void conv_silu_kernel(const float* __restrict__ conv_w,
                                 const float* __restrict__ conv_b)
{
    int idx = blockIdx.x * blockDim.x + threadIdx.x;
    if (idx >= MROWS * DI) return;
    int d  = idx % DI;
    int bl = idx / DI;
    int l  = bl & (Lsz - 1);

    float acc = conv_b[d];
    #pragma unroll
    for (int j = 0; j < 4; j++) {
        int ll = l - 3 + j;
        if (ll >= 0)
            acc += conv_w[d * 4 + j] * g_xz[(size_t)(bl - 3 + j) * (2 * DI) + d];
    }
    g_xssm[idx] = acc / (1.f + expf(-acc));
}

// ---------------------------------------------------------------------------
// 7a) scan pass 1: per (pair, chunk) local scan from h=0; record hend + prod dA.
// group = 4 lanes, 4 states/lane.  idx = chunk * NPAIR + pair (pair-major
// within a warp -> coalesced dt/x; B is a batch-level broadcast).
// ---------------------------------------------------------------------------
#define PF 8

__global__ void __launch_bounds__(128)
scan_p1_kernel(const float* __restrict__ A_log)
{
    int idx = blockIdx.x * 32 + (threadIdx.x >> 2);
    if (idx >= NPAIR * NCH) return;
    int ln    = threadIdx.x & 3;
    int pair  = idx % NPAIR;
    int chunk = idx / NPAIR;
    int b = pair / DI;
    int d = pair % DI;
    int n0 = ln * 4;
    int lbase = chunk * CL;

    float Av[4], h[4], P[4];
    #pragma unroll
    for (int j = 0; j < 4; j++) {
        Av[j] = -expf(A_log[d * DS + n0 + j]);
        h[j] = 0.f;
        P[j] = 1.f;
    }

    const float* dtp = g_dt   + (size_t)b * Lsz * DI + (size_t)lbase * DI + d;
    const float* xp  = g_xssm + (size_t)b * Lsz * DI + (size_t)lbase * DI + d;
    const float* dbl = g_xdbl + (size_t)b * Lsz * 80 + (size_t)lbase * 80;

    float  pdt[PF], px[PF];
    float4 pB[PF];
    #pragma unroll
    for (int j = 0; j < PF; j++) {
        pdt[j] = dtp[(size_t)j * DI];
        px[j]  = xp [(size_t)j * DI];
        pB[j]  = *reinterpret_cast<const float4*>(&dbl[j * 80 + DTR + n0]);
    }

    for (int l0 = 0; l0 < CL; l0 += PF) {
        #pragma unroll
        for (int j = 0; j < PF; j++) {
            const int l = l0 + j;
            float  dt_t = pdt[j];
            float  x_t  = px[j];
            float4 Bv   = pB[j];
            const int lf = l + PF;
            if (lf < CL) {
                pdt[j] = dtp[(size_t)lf * DI];
                px[j]  = xp [(size_t)lf * DI];
                pB[j]  = *reinterpret_cast<const float4*>(&dbl[lf * 80 + DTR + n0]);
            }
            float dtx = dt_t * x_t;
            float a0 = expf(dt_t * Av[0]);
            float a1 = expf(dt_t * Av[1]);
            float a2 = expf(dt_t * Av[2]);
            float a3 = expf(dt_t * Av[3]);
            h[0] = a0 * h[0] + dtx * Bv.x;  P[0] *= a0;
            h[1] = a1 * h[1] + dtx * Bv.y;  P[1] *= a1;
            h[2] = a2 * h[2] + dtx * Bv.z;  P[2] *= a2;
            h[3] = a3 * h[3] + dtx * Bv.w;  P[3] *= a3;
        }
    }

    size_t base = ((size_t)pair * NCH + chunk) * DS + n0;
    *reinterpret_cast<float4*>(&g_hend [base]) = make_float4(h[0], h[1], h[2], h[3]);
    *reinterpret_cast<float4*>(&g_Pprod[base]) = make_float4(P[0], P[1], P[2], P[3]);
}

// ---------------------------------------------------------------------------
// 7b) scan pass 2: sequential combine across the 8 chunks per (pair,state).
// ---------------------------------------------------------------------------
__global__ void scan_p2_kernel()
{
    int idx = blockIdx.x * blockDim.x + threadIdx.x;   // (pair, state)
    if (idx >= NPAIR * DS) return;
    int pair = idx / DS;
    int s    = idx % DS;
    float hs = 0.f;
    #pragma unroll
    for (int c = 0; c < NCH; c++) {
        size_t o = ((size_t)pair * NCH + c) * DS + s;
        g_hstart[o] = hs;
        hs = g_Pprod[o] * hs + g_hend[o];
    }
}

// ---------------------------------------------------------------------------
// 7c) scan pass 3: re-scan each chunk from its true hstart; emit y.
// ---------------------------------------------------------------------------
__global__ void __launch_bounds__(128)
scan_p3_kernel(const float* __restrict__ A_log,
               const float* __restrict__ Dw)
{
    int idx = blockIdx.x * 32 + (threadIdx.x >> 2);
    if (idx >= NPAIR * NCH) return;
    int ln    = threadIdx.x & 3;
    int pair  = idx % NPAIR;
    int chunk = idx / NPAIR;
    int b = pair / DI;
    int d = pair % DI;
    int n0 = ln * 4;
    int lbase = chunk * CL;

    float Av[4], h[4];
    size_t hsbase = ((size_t)pair * NCH + chunk) * DS + n0;
    float4 hs = *reinterpret_cast<const float4*>(&g_hstart[hsbase]);
    h[0] = hs.x; h[1] = hs.y; h[2] = hs.z; h[3] = hs.w;
    #pragma unroll
    for (int j = 0; j < 4; j++)
        Av[j] = -expf(A_log[d * DS + n0 + j]);
    float Dd = Dw[d];

    const float* dtp = g_dt   + (size_t)b * Lsz * DI + (size_t)lbase * DI + d;
    const float* xp  = g_xssm + (size_t)b * Lsz * DI + (size_t)lbase * DI + d;
    const float* dbl = g_xdbl + (size_t)b * Lsz * 80 + (size_t)lbase * 80;
    const float* zp  = g_xz   + (size_t)b * Lsz * (2 * DI) + (size_t)lbase * (2 * DI) + DI + d;
    __nv_bfloat16* yp = g_y_bf + (size_t)b * Lsz * DI + (size_t)lbase * DI + d;

    float  pdt[PF], px[PF], pz[PF];
    float4 pB[PF], pC[PF];
    #pragma unroll
    for (int j = 0; j < PF; j++) {
        pdt[j] = dtp[(size_t)j * DI];
        px[j]  = xp [(size_t)j * DI];
        pB[j]  = *reinterpret_cast<const float4*>(&dbl[j * 80 + DTR + n0]);
        pC[j]  = *reinterpret_cast<const float4*>(&dbl[j * 80 + DTR + DS + n0]);
        pz[j]  = zp[(size_t)j * (2 * DI)];
    }

    for (int l0 = 0; l0 < CL; l0 += PF) {
        #pragma unroll
        for (int j = 0; j < PF; j++) {
            const int l = l0 + j;
            float  dt_t = pdt[j];
            float  x_t  = px[j];
            float4 Bv   = pB[j];
            float4 Cv   = pC[j];
            float  zv   = pz[j];
            const int lf = l + PF;
            if (lf < CL) {
                pdt[j] = dtp[(size_t)lf * DI];
                px[j]  = xp [(size_t)lf * DI];
                pB[j]  = *reinterpret_cast<const float4*>(&dbl[lf * 80 + DTR + n0]);
                pC[j]  = *reinterpret_cast<const float4*>(&dbl[lf * 80 + DTR + DS + n0]);
                pz[j]  = zp[(size_t)lf * (2 * DI)];
            }
            float dtx = dt_t * x_t;
            h[0] = expf(dt_t * Av[0]) * h[0] + dtx * Bv.x;
            h[1] = expf(dt_t * Av[1]) * h[1] + dtx * Bv.y;
            h[2] = expf(dt_t * Av[2]) * h[2] + dtx * Bv.z;
            h[3] = expf(dt_t * Av[3]) * h[3] + dtx * Bv.w;
            float part = h[0] * Cv.x + h[1] * Cv.y + h[2] * Cv.z + h[3] * Cv.w;
            part += __shfl_xor_sync(0xFFFFFFFFu, part, 2);
            part += __shfl_xor_sync(0xFFFFFFFFu, part, 1);
            if (ln == 0) {
                float sz = zv / (1.f + expf(-zv));
                yp[(size_t)l * DI] = __float2bfloat16_rn((part + Dd * x_t) * sz);
            }
        }
    }
}

// ---------------------------------------------------------------------------
extern "C" void kernel_launch(void* const* d_in, const int* in_sizes, int n_in,
                              void* d_out, int out_size)
{
    const float* x      = (const float*)d_in[0];
    const float* gamma  = (const float*)d_in[1];
    const float* beta   = (const float*)d_in[2];
    const float* W_in   = (const float*)d_in[3];
    const float* conv_w = (const float*)d_in[4];
    const float* conv_b = (const float*)d_in[5];
    const float* W_xproj= (const float*)d_in[6];
    const float* W_dt   = (const float*)d_in[7];
    const float* b_dt   = (const float*)d_in[8];
    const float* A_log  = (const float*)d_in[9];
    const float* Dw     = (const float*)d_in[10];
    const float* W_out  = (const float*)d_in[11];
    float* out = (float*)d_out;

    static float *xz = nullptr, *xssm = nullptr, *xdbl = nullptr,
                 *xdbl_part = nullptr, *dtb = nullptr;
    static __nv_bfloat16 *hn_bf = nullptr, *Win_bf = nullptr,
                         *Wout_bf = nullptr, *y_bf = nullptr;
    if (!xz) {
        cudaGetSymbolAddress((void**)&xz,        g_xz);
        cudaGetSymbolAddress((void**)&xssm,      g_xssm);
        cudaGetSymbolAddress((void**)&xdbl,      g_xdbl);
        cudaGetSymbolAddress((void**)&xdbl_part, g_xdbl_part);
        cudaGetSymbolAddress((void**)&dtb,       g_dt);
        cudaGetSymbolAddress((void**)&hn_bf,     g_hn_bf);
        cudaGetSymbolAddress((void**)&Win_bf,    g_Win_bf);
        cudaGetSymbolAddress((void**)&Wout_bf,   g_Wout_bf);
        cudaGetSymbolAddress((void**)&y_bf,      g_y_bf);
        cudaFuncSetAttribute(gemm_bf16<0>,
                             cudaFuncAttributeMaxDynamicSharedMemorySize, GSMEM_BF);
        cudaFuncSetAttribute(gemm_bf16<2>,
                             cudaFuncAttributeMaxDynamicSharedMemorySize, GSMEM_BF);
        cudaFuncSetAttribute(gemm_tf32<128, 2, 2, 1>,
                             cudaFuncAttributeMaxDynamicSharedMemorySize, GSMEM(128));
        cudaFuncSetAttribute(gemm_tf32<80, 4, 1, 0>,
                             cudaFuncAttributeMaxDynamicSharedMemorySize, GSMEM(80));
    }

    // 0) convert W_in to bf16 (keeps GEMM1 at profiled launch index 3)
    cvt_bf16_kernel<<<(2 * DI * DM + 255) / 256, 256>>>(W_in, Win_bf, 2 * DI * DM);
    // 1) LN stats
    ln_stats_kernel<<<dim3(Lsz / 64, Bsz), 256>>>(x);
    // 2) transpose + LN apply (bf16 out)
    ln_apply_kernel<<<dim3(Lsz / 32, DM / 32, Bsz), dim3(32, 8)>>>(x, gamma, beta);
    // 3) GEMM1 (bf16): xz = hn @ W_in^T   (4096 x 3072 x 768)
    gemm_bf16<0><<<dim3(3072 / 128, MROWS / 128), 128, GSMEM_BF>>>(
        hn_bf, DM, Win_bf, DM, xz, 2 * DI, DM, nullptr);
    // 4) conv + silu
    conv_silu_kernel<<<(MROWS * DI + 255) / 256, 256>>>(conv_w, conv_b);
    // 5) xproj split-K x6 + reduce
    gemm_tf32<80, 4, 1, 0><<<dim3(1, MROWS / 128, SPLITK), 128, GSMEM(80)>>>(
        xssm, DI, W_xproj, DI, xdbl_part, 80, XPK, nullptr, MROWS * 80);
    xdbl_reduce_kernel<<<(MROWS * 80 + 255) / 256, 256>>>();
    // 6) dt = softplus(xdbl[:, :48] @ W_dt^T + b_dt)
    gemm_tf32<128, 2, 2, 1><<<dim3(DI / 128, MROWS / 128), 128, GSMEM(128)>>>(
        xdbl, 80, W_dt, DTR, dtb, DI, DTR, b_dt, 0);
    // 6.5) convert W_out to bf16
    cvt_bf16_kernel<<<(DM * DI + 255) / 256, 256>>>(W_out, Wout_bf, DM * DI);
    // 7) chunked parallel scan (3 passes)
    scan_p1_kernel<<<(NPAIR * NCH) / 32, 128>>>(A_log);
    scan_p2_kernel<<<(NPAIR * DS + 255) / 256, 256>>>();
    scan_p3_kernel<<<(NPAIR * NCH) / 32, 128>>>(A_log, Dw);
    // 8) GEMM out (bf16): out = y @ W_out^T, transpose + residual
    gemm_bf16<2><<<dim3(DM / 128, MROWS / 128), 128, GSMEM_BF>>>(
        y_bf, DI, Wout_bf, DI, out, 0, DI, x);
}